// round 1
// baseline (speedup 1.0000x reference)
#include <cuda_runtime.h>
#include <cstdint>
#include <cstddef>

// Problem dims (fixed by the reference)
#define BATCH_B 4
#define SEQ_J   2048
#define BJ      8192      // B*J rows of x
#define MDIM    4096      // d_model (stage-1 contraction)
#define KDIM    4096      // out dim
#define NADPT   4
#define DR      16        // lora rank
#define NDALL   64        // NADPT*DR

// 2 MB scratch for t[n][bj][d]  (allowed: __device__ global, no allocs)
__device__ float g_t[NADPT * BJ * DR];

// ---------------------------------------------------------------------------
// helpers
// ---------------------------------------------------------------------------
__device__ __forceinline__ void split_tf32(float v, uint32_t& hi, uint32_t& lo) {
    uint32_t h;
    asm("cvt.rna.tf32.f32 %0, %1;" : "=r"(h) : "f"(v));
    float r = v - __uint_as_float(h);   // tf32 value is exactly representable in f32
    asm("cvt.rna.tf32.f32 %0, %1;" : "=r"(lo) : "f"(r));
    hi = h;
}

__device__ __forceinline__ void mma8(float c[4], const uint32_t a[4], const uint32_t b[2]) {
    asm volatile(
        "mma.sync.aligned.m16n8k8.row.col.f32.tf32.tf32.f32 "
        "{%0,%1,%2,%3}, {%4,%5,%6,%7}, {%8,%9}, {%0,%1,%2,%3};\n"
        : "+f"(c[0]), "+f"(c[1]), "+f"(c[2]), "+f"(c[3])
        : "r"(a[0]), "r"(a[1]), "r"(a[2]), "r"(a[3]), "r"(b[0]), "r"(b[1]));
}

// ---------------------------------------------------------------------------
// Stage 1:  T[bj][nd] = X[bj][m] @ Aall[nd][m]^T    (nd = n*16+d, NDALL=64)
// Block: 64 bj rows x all 64 nd cols, k-loop over M in chunks of 32.
// Split-tf32 (3 mma passes) for fp32-level accuracy.
// ---------------------------------------------------------------------------
__global__ __launch_bounds__(256)
void lora_stage1(const float* __restrict__ x, const float* __restrict__ Aall) {
    __shared__ float Xs[64 * 36];   // stride 36 -> conflict-free frag loads
    __shared__ float As[64 * 36];

    const int tid  = threadIdx.x;
    const int lane = tid & 31;
    const int warp = tid >> 5;
    const int gid  = lane >> 2;     // quad id (0..7)
    const int tig  = lane & 3;      // thread-in-quad
    const int wm   = warp & 1;      // 2 warps over 64 bj (32 each)
    const int wn   = warp >> 1;     // 4 warps over 64 nd (16 each)
    const int bj0  = blockIdx.x * 64;

    // loader mapping: 512 float4 per chunk, 2 per thread
    const int r0 = tid >> 3;          // 0..31
    const int lc = (tid & 7) * 4;     // float col within 32-chunk

    const float* xp0 = x    + (size_t)(bj0 + r0)      * MDIM + lc;
    const float* xp1 = x    + (size_t)(bj0 + r0 + 32) * MDIM + lc;
    const float* ap0 = Aall + (size_t)(r0)            * MDIM + lc;
    const float* ap1 = Aall + (size_t)(r0 + 32)       * MDIM + lc;

    float acc[2][2][4];
#pragma unroll
    for (int i = 0; i < 2; ++i)
#pragma unroll
        for (int j = 0; j < 2; ++j)
#pragma unroll
            for (int q = 0; q < 4; ++q) acc[i][j][q] = 0.0f;

    // software pipeline: stage next chunk in registers while computing current
    float4 xr0 = *(const float4*)(xp0);
    float4 xr1 = *(const float4*)(xp1);
    float4 ar0 = *(const float4*)(ap0);
    float4 ar1 = *(const float4*)(ap1);
    *(float4*)&Xs[r0 * 36 + lc]        = xr0;
    *(float4*)&Xs[(r0 + 32) * 36 + lc] = xr1;
    *(float4*)&As[r0 * 36 + lc]        = ar0;
    *(float4*)&As[(r0 + 32) * 36 + lc] = ar1;
    __syncthreads();

    for (int kc = 0; kc < MDIM; kc += 32) {
        const bool more = (kc + 32) < MDIM;
        if (more) {
            xr0 = *(const float4*)(xp0 + kc + 32);
            xr1 = *(const float4*)(xp1 + kc + 32);
            ar0 = *(const float4*)(ap0 + kc + 32);
            ar1 = *(const float4*)(ap1 + kc + 32);
        }

#pragma unroll
        for (int kk = 0; kk < 32; kk += 8) {
            uint32_t ahi[2][4], alo[2][4], bhi[2][2], blo[2][2];
#pragma unroll
            for (int mi = 0; mi < 2; ++mi) {
                const int rb = (wm * 32 + mi * 16 + gid) * 36;
                split_tf32(Xs[rb + kk + tig],              ahi[mi][0], alo[mi][0]);
                split_tf32(Xs[rb + 8 * 36 + kk + tig],     ahi[mi][1], alo[mi][1]);
                split_tf32(Xs[rb + kk + 4 + tig],          ahi[mi][2], alo[mi][2]);
                split_tf32(Xs[rb + 8 * 36 + kk + 4 + tig], ahi[mi][3], alo[mi][3]);
            }
#pragma unroll
            for (int ni = 0; ni < 2; ++ni) {
                const int cb = (wn * 16 + ni * 8 + gid) * 36;
                split_tf32(As[cb + kk + tig],     bhi[ni][0], blo[ni][0]);
                split_tf32(As[cb + kk + 4 + tig], bhi[ni][1], blo[ni][1]);
            }
#pragma unroll
            for (int mi = 0; mi < 2; ++mi)
#pragma unroll
                for (int ni = 0; ni < 2; ++ni) {
                    mma8(acc[mi][ni], ahi[mi], bhi[ni]);
                    mma8(acc[mi][ni], alo[mi], bhi[ni]);
                    mma8(acc[mi][ni], ahi[mi], blo[ni]);
                }
        }
        __syncthreads();
        if (more) {
            *(float4*)&Xs[r0 * 36 + lc]        = xr0;
            *(float4*)&Xs[(r0 + 32) * 36 + lc] = xr1;
            *(float4*)&As[r0 * 36 + lc]        = ar0;
            *(float4*)&As[(r0 + 32) * 36 + lc] = ar1;
            __syncthreads();
        }
    }

    // epilogue: scatter into t[n][bj][d]
#pragma unroll
    for (int mi = 0; mi < 2; ++mi)
#pragma unroll
        for (int ni = 0; ni < 2; ++ni) {
            const int row = bj0 + wm * 32 + mi * 16 + gid;
            const int col = wn * 16 + ni * 8 + 2 * tig;   // nd, even
            const int n = col >> 4, d = col & 15;
            float2 v01 = make_float2(acc[mi][ni][0], acc[mi][ni][1]);
            float2 v23 = make_float2(acc[mi][ni][2], acc[mi][ni][3]);
            *(float2*)&g_t[((size_t)(n * BJ) + row) * DR + d]     = v01;
            *(float2*)&g_t[((size_t)(n * BJ) + row + 8) * DR + d] = v23;
        }
}

// ---------------------------------------------------------------------------
// Stage 2: per adapter n:  Out_n[bj][k] = T_n[bj][d] @ Bm_n[k][d]^T   (d=16)
// Block tile 128 bj x 64 k; 8 warps = 4(bj) x 2(k), warp tile 32x32.
// Store-bandwidth bound (512 MB out) — keep occupancy >=2 to hide fill latency.
// ---------------------------------------------------------------------------
__global__ __launch_bounds__(256)
void lora_stage2(const float* __restrict__ Bm, float* __restrict__ out) {
    __shared__ float Ts[128 * 20];  // stride 20 -> conflict-free
    __shared__ float Bs[64 * 20];

    const int tid  = threadIdx.x;
    const int lane = tid & 31;
    const int warp = tid >> 5;
    const int gid  = lane >> 2;
    const int tig  = lane & 3;
    const int wn   = warp & 1;      // 2 warps over 64 k (32 each)
    const int wm   = warp >> 1;     // 4 warps over 128 bj (32 each)

    const int n   = blockIdx.z;
    const int bj0 = blockIdx.y * 128;
    const int k0  = blockIdx.x * 64;

    {
        const int r = tid >> 2;           // 0..63
        const int c = (tid & 3) * 4;      // 0,4,8,12
        *(float4*)&Ts[r * 20 + c] =
            *(const float4*)&g_t[((size_t)(n * BJ) + bj0 + r) * DR + c];
        *(float4*)&Ts[(r + 64) * 20 + c] =
            *(const float4*)&g_t[((size_t)(n * BJ) + bj0 + r + 64) * DR + c];
        *(float4*)&Bs[r * 20 + c] =
            *(const float4*)&Bm[((size_t)(n * KDIM) + k0 + r) * DR + c];
    }
    __syncthreads();

    float acc[2][4][4];
#pragma unroll
    for (int i = 0; i < 2; ++i)
#pragma unroll
        for (int j = 0; j < 4; ++j)
#pragma unroll
            for (int q = 0; q < 4; ++q) acc[i][j][q] = 0.0f;

#pragma unroll
    for (int kk = 0; kk < 16; kk += 8) {
        uint32_t ahi[2][4], alo[2][4], bhi[4][2], blo[4][2];
#pragma unroll
        for (int mi = 0; mi < 2; ++mi) {
            const int rb = (wm * 32 + mi * 16 + gid) * 20;
            split_tf32(Ts[rb + kk + tig],              ahi[mi][0], alo[mi][0]);
            split_tf32(Ts[rb + 8 * 20 + kk + tig],     ahi[mi][1], alo[mi][1]);
            split_tf32(Ts[rb + kk + 4 + tig],          ahi[mi][2], alo[mi][2]);
            split_tf32(Ts[rb + 8 * 20 + kk + 4 + tig], ahi[mi][3], alo[mi][3]);
        }
#pragma unroll
        for (int ni = 0; ni < 4; ++ni) {
            const int cb = (wn * 32 + ni * 8 + gid) * 20;
            split_tf32(Bs[cb + kk + tig],     bhi[ni][0], blo[ni][0]);
            split_tf32(Bs[cb + kk + 4 + tig], bhi[ni][1], blo[ni][1]);
        }
#pragma unroll
        for (int mi = 0; mi < 2; ++mi)
#pragma unroll
            for (int ni = 0; ni < 4; ++ni) {
                mma8(acc[mi][ni], ahi[mi], bhi[ni]);
                mma8(acc[mi][ni], alo[mi], bhi[ni]);
                mma8(acc[mi][ni], ahi[mi], blo[ni]);
            }
    }

#pragma unroll
    for (int mi = 0; mi < 2; ++mi)
#pragma unroll
        for (int ni = 0; ni < 4; ++ni) {
            const int row = bj0 + wm * 32 + mi * 16 + gid;
            const int col = k0 + wn * 32 + ni * 8 + 2 * tig;
            const size_t base = ((size_t)n * BJ + row) * (size_t)KDIM + col;
            *(float2*)&out[base]              = make_float2(acc[mi][ni][0], acc[mi][ni][1]);
            *(float2*)&out[base + 8 * KDIM]   = make_float2(acc[mi][ni][2], acc[mi][ni][3]);
        }
}

// ---------------------------------------------------------------------------
extern "C" void kernel_launch(void* const* d_in, const int* in_sizes, int n_in,
                              void* d_out, int out_size) {
    const float* x    = (const float*)d_in[0];   // [B,J,M]  = [8192,4096] rows
    const float* Aall = (const float*)d_in[1];   // [N,D,M]  = [64,4096] rows
    const float* Bm   = (const float*)d_in[2];   // [N,K,D]  = [4,4096,16]
    float* out = (float*)d_out;                  // [N,B,J,K]

    lora_stage1<<<BJ / 64, 256>>>(x, Aall);
    dim3 g2(KDIM / 64, BJ / 128, NADPT);
    lora_stage2<<<g2, 256>>>(Bm, out);
}